// round 15
// baseline (speedup 1.0000x reference)
#include <cuda_runtime.h>
#include <cuda_bf16.h>
#include <cstdint>

// ---------------------------------------------------------------------------
// 2-layer LSTM: B=64, T=512, D=H=1024.  HMMA (mma.sync) path.
// R15 = R12 trunk + ONE change: recurrence pipeline processes stages in PAIRS
// (ring depth 6, 16 sync rounds/step instead of 32, same 10KB stages, same
// accumulation order -> bit-identical). Barrier/GEMM/pointwise = R12 verbatim.
// ---------------------------------------------------------------------------

#define B_DIM 64
#define T_DIM 512
#define H_DIM 1024
#define G_DIM 4096
#define M_TOT (B_DIM * T_DIM)   // 32768
#define NCTA 128

#define WS 1032          // padded W row stride (bf16 elems)
#define SA 40            // padded H stage row stride (elems)
#define STG_E (64 * SA)  // 2560 elems per hi (or lo) stage
#define NSTAGE 6         // ring of 3 pairs
#define SMEM_SEQ (32 * WS * 2 * 2 + NSTAGE * 2 * STG_E * 2 + 64 * 33 * 4) // 201984

// -------------------- device scratch (no allocs allowed) -------------------
__device__ __nv_bfloat16 g_Ahi[(size_t)M_TOT * H_DIM];   // X split, then out0 split
__device__ __nv_bfloat16 g_Alo[(size_t)M_TOT * H_DIM];
__device__ float         g_xg [(size_t)M_TOT * G_DIM];   // gate pre-activations
__device__ __nv_bfloat16 g_Whi[(size_t)4 * G_DIM * H_DIM];  // Wih0,Whh0,Wih1,Whh1
__device__ __nv_bfloat16 g_Wlo[(size_t)4 * G_DIM * H_DIM];
__device__ float         g_c[B_DIM * H_DIM];
__device__ float         g_h[B_DIM * H_DIM];
__device__ __nv_bfloat16 g_hhi[2][B_DIM * H_DIM];        // double-buffered h split
__device__ __nv_bfloat16 g_hlo[2][B_DIM * H_DIM];
__device__ volatile unsigned g_bar_count;

extern __shared__ char smem_raw[];

// -------------------- PTX helpers ------------------------------------------
__device__ __forceinline__ void mma_bf16(float (&d)[4], const uint32_t (&a)[4],
                                         uint32_t b0, uint32_t b1) {
    asm volatile(
        "mma.sync.aligned.m16n8k16.row.col.f32.bf16.bf16.f32 "
        "{%0,%1,%2,%3}, {%4,%5,%6,%7}, {%8,%9}, {%0,%1,%2,%3};\n"
        : "+f"(d[0]), "+f"(d[1]), "+f"(d[2]), "+f"(d[3])
        : "r"(a[0]), "r"(a[1]), "r"(a[2]), "r"(a[3]), "r"(b0), "r"(b1));
}
__device__ __forceinline__ void ldsm4(uint32_t (&r)[4], const __nv_bfloat16* p) {
    uint32_t a = (uint32_t)__cvta_generic_to_shared(p);
    asm volatile("ldmatrix.sync.aligned.m8n8.x4.shared.b16 {%0,%1,%2,%3}, [%4];"
                 : "=r"(r[0]), "=r"(r[1]), "=r"(r[2]), "=r"(r[3]) : "r"(a));
}
__device__ __forceinline__ void cpasync16(uint32_t dst, const void* src) {
    asm volatile("cp.async.cg.shared.global [%0], [%1], 16;" :: "r"(dst), "l"(src));
}
__device__ __forceinline__ void cp_commit() {
    asm volatile("cp.async.commit_group;");
}
template <int N>
__device__ __forceinline__ void cp_wait() {
    asm volatile("cp.async.wait_group %0;" :: "n"(N));
}

// -------------------- fused split: all 5 tensors in one launch --------------
__global__ void split_all_kernel(const float* __restrict__ X,
                                 const float* __restrict__ Wa,
                                 const float* __restrict__ Wb,
                                 const float* __restrict__ Wc,
                                 const float* __restrict__ Wd) {
    const size_t NQX = (size_t)M_TOT * H_DIM / 4;       // 8388608
    const size_t NQW = (size_t)G_DIM * H_DIM / 4;       // 1048576 = 1<<20
    const size_t TOT = NQX + 4 * NQW;
    for (size_t q = (size_t)blockIdx.x * blockDim.x + threadIdx.x; q < TOT;
         q += (size_t)gridDim.x * blockDim.x) {
        const float* src;
        __nv_bfloat16 *hi, *lo;
        size_t i;
        if (q < NQX) {
            src = X; i = q * 4; hi = g_Ahi; lo = g_Alo;
        } else {
            const size_t r = q - NQX;
            const int seg = (int)(r >> 20);
            i = (r - ((size_t)seg << 20)) * 4;
            src = (seg == 0) ? Wa : (seg == 1) ? Wb : (seg == 2) ? Wc : Wd;
            hi = g_Whi + (size_t)seg * G_DIM * H_DIM;
            lo = g_Wlo + (size_t)seg * G_DIM * H_DIM;
        }
        float4 v = *(const float4*)(src + i);
        __nv_bfloat16 h0 = __float2bfloat16(v.x);
        __nv_bfloat16 h1 = __float2bfloat16(v.y);
        __nv_bfloat16 h2 = __float2bfloat16(v.z);
        __nv_bfloat16 h3 = __float2bfloat16(v.w);
        __nv_bfloat16 l0 = __float2bfloat16(v.x - __bfloat162float(h0));
        __nv_bfloat16 l1 = __float2bfloat16(v.y - __bfloat162float(h1));
        __nv_bfloat16 l2 = __float2bfloat16(v.z - __bfloat162float(h2));
        __nv_bfloat16 l3 = __float2bfloat16(v.w - __bfloat162float(h3));
        __nv_bfloat162* ph = reinterpret_cast<__nv_bfloat162*>(hi + i);
        __nv_bfloat162* pl = reinterpret_cast<__nv_bfloat162*>(lo + i);
        ph[0] = __halves2bfloat162(h0, h1);
        ph[1] = __halves2bfloat162(h2, h3);
        pl[0] = __halves2bfloat162(l0, l1);
        pl[1] = __halves2bfloat162(l2, l3);
    }
}

__global__ void zero_state_kernel() {
    int i = blockIdx.x * blockDim.x + threadIdx.x;
    if (i == 0) g_bar_count = 0u;
    if (i < B_DIM * H_DIM) {
        g_h[i] = 0.f; g_c[i] = 0.f;
        __nv_bfloat16 z = __float2bfloat16(0.f);
        g_hhi[0][i] = z; g_hhi[1][i] = z;
        g_hlo[0][i] = z; g_hlo[1][i] = z;
    }
}

__global__ void copy_state_kernel(float* __restrict__ dh, float* __restrict__ dc) {
    int i = blockIdx.x * blockDim.x + threadIdx.x;
    if (i < B_DIM * H_DIM) { dh[i] = g_h[i]; dc[i] = g_c[i]; }
}

// -------------------- big GEMM: g_xg = A @ W^T + b1 + b2 (R7 verbatim) -----
__global__ __launch_bounds__(256) void gemm_xg_kernel(int wsel,
                                                      const float* __restrict__ b1,
                                                      const float* __restrict__ b2) {
    constexpr int BM = 64, BN = 64, BK = 32, GSA = 40, GSB = 40;
    constexpr int K = H_DIM, NKB = K / BK;
    __shared__ __nv_bfloat16 sAh[2][BM * GSA];
    __shared__ __nv_bfloat16 sAl[2][BM * GSA];
    __shared__ __nv_bfloat16 sBh[2][BN * GSB];
    __shared__ __nv_bfloat16 sBl[2][BN * GSB];

    const int m0 = blockIdx.y * BM;
    const int n0 = blockIdx.x * BN;
    const int tid = threadIdx.x;
    const int lane = tid & 31, wid = tid >> 5;
    const int wr = wid & 1;        // m strip (2 x 32)
    const int wc = wid >> 1;       // n strip (4 x 16)
    const int gid = lane >> 2, tg = lane & 3;

    const int aofs = (lane & 15) * GSA + (lane >> 4) * 8;
    const int bofs = (lane & 15) * GSB + (lane >> 4) * 8;

    const size_t woff = (size_t)wsel * G_DIM * H_DIM;
    const __nv_bfloat16* __restrict__ Wh = g_Whi + woff;
    const __nv_bfloat16* __restrict__ Wl = g_Wlo + woff;

    const int lrow = tid >> 2, lvec = tid & 3;            // 64 rows x 4 uint4
    const size_t aoff = (size_t)(m0 + lrow) * K + lvec * 8;
    const size_t boff = (size_t)(n0 + lrow) * K + lvec * 8;
    const int soff = lrow * GSA + lvec * 8;

    float acc[2][2][4];
#pragma unroll
    for (int i = 0; i < 2; i++)
#pragma unroll
        for (int j = 0; j < 2; j++)
#pragma unroll
            for (int q = 0; q < 4; q++) acc[i][j][q] = 0.f;

    uint4 rAh, rAl, rBh, rBl;
    rAh = *(const uint4*)(g_Ahi + aoff);
    rAl = *(const uint4*)(g_Alo + aoff);
    rBh = *(const uint4*)(Wh + boff);
    rBl = *(const uint4*)(Wl + boff);
    *(uint4*)&sAh[0][soff] = rAh;
    *(uint4*)&sAl[0][soff] = rAl;
    *(uint4*)&sBh[0][soff] = rBh;
    *(uint4*)&sBl[0][soff] = rBl;
    __syncthreads();

    for (int kb = 0; kb < NKB; ++kb) {
        const int buf = kb & 1;
        if (kb + 1 < NKB) {
            const size_t k2 = (size_t)(kb + 1) * BK;
            rAh = *(const uint4*)(g_Ahi + aoff + k2);
            rAl = *(const uint4*)(g_Alo + aoff + k2);
            rBh = *(const uint4*)(Wh + boff + k2);
            rBl = *(const uint4*)(Wl + boff + k2);
        }
#pragma unroll
        for (int ks = 0; ks < 2; ++ks) {
            const int k16 = ks * 16;
            uint32_t ah[2][4], al[2][4], tbh[4], tbl[4];
#pragma unroll
            for (int im = 0; im < 2; ++im) {
                const int mrow = wr * 32 + im * 16;
                ldsm4(ah[im], &sAh[buf][mrow * GSA + k16 + aofs]);
                ldsm4(al[im], &sAl[buf][mrow * GSA + k16 + aofs]);
            }
            ldsm4(tbh, &sBh[buf][(wc * 16) * GSB + k16 + bofs]);
            ldsm4(tbl, &sBl[buf][(wc * 16) * GSB + k16 + bofs]);
#pragma unroll
            for (int im = 0; im < 2; ++im) {
                mma_bf16(acc[im][0], ah[im], tbh[0], tbh[2]);
                mma_bf16(acc[im][0], ah[im], tbl[0], tbl[2]);
                mma_bf16(acc[im][0], al[im], tbh[0], tbh[2]);
                mma_bf16(acc[im][1], ah[im], tbh[1], tbh[3]);
                mma_bf16(acc[im][1], ah[im], tbl[1], tbl[3]);
                mma_bf16(acc[im][1], al[im], tbh[1], tbh[3]);
            }
        }
        if (kb + 1 < NKB) {
            const int nb = buf ^ 1;
            *(uint4*)&sAh[nb][soff] = rAh;
            *(uint4*)&sAl[nb][soff] = rAl;
            *(uint4*)&sBh[nb][soff] = rBh;
            *(uint4*)&sBl[nb][soff] = rBl;
        }
        __syncthreads();
    }

#pragma unroll
    for (int im = 0; im < 2; ++im)
#pragma unroll
        for (int in_ = 0; in_ < 2; ++in_) {
            const int row = m0 + wr * 32 + im * 16 + gid;
            const int col = n0 + wc * 16 + in_ * 8 + tg * 2;
            const float bb0 = b1[col] + b2[col];
            const float bb1 = b1[col + 1] + b2[col + 1];
            float2 v0 = make_float2(acc[im][in_][0] + bb0, acc[im][in_][1] + bb1);
            float2 v1 = make_float2(acc[im][in_][2] + bb0, acc[im][in_][3] + bb1);
            *(float2*)&g_xg[(size_t)row * G_DIM + col] = v0;
            *(float2*)&g_xg[(size_t)(row + 8) * G_DIM + col] = v1;
        }
}

// -------------------- persistent recurrence kernel (R12 + paired stages) ----
__global__ __launch_bounds__(256) void lstm_seq_kernel(int wsel, int layer,
                                                       float* __restrict__ out) {
    constexpr int BK = 32, K = H_DIM, NKB = K / BK;
    __nv_bfloat16* sWh = (__nv_bfloat16*)smem_raw;                    // 32*WS
    __nv_bfloat16* sWl = sWh + 32 * WS;                               // 32*WS
    __nv_bfloat16* sH  = sWl + 32 * WS;          // NSTAGE*(hi+lo) stages
    float*         sG  = (float*)(sH + NSTAGE * 2 * STG_E);          // 64*33

    const int nblk = blockIdx.x;
    const int tid = threadIdx.x;
    const int lane = tid & 31, wid = tid >> 5;
    const int wr = wid & 3;          // 4 m-strips of 16 rows
    const int wc = wid >> 2;         // 2 n-strips of 16 cols
    const int gid = lane >> 2, tg = lane & 3;

    const int aofs = (lane & 15) * SA + (lane >> 4) * 8;      // H ldsm lane ofs
    const int wofs = (wc * 16 + (lane & 15)) * WS + (lane >> 4) * 8;  // W lane ofs

    const size_t woff = (size_t)wsel * G_DIM * H_DIM;

    // ---- load W_hh slice into smem (once) ----
    {
        const int wrow = tid >> 3, wvec = tid & 7;
        const int gsel = wrow >> 3, r8 = wrow & 7;
        const size_t grow = woff + (size_t)(gsel * H_DIM + nblk * 8 + r8) * K;
#pragma unroll 4
        for (int k = wvec * 4; k < K; k += 32) {
            *(uint2*)&sWh[wrow * WS + k] = *(const uint2*)(g_Whi + grow + k);
            *(uint2*)&sWl[wrow * WS + k] = *(const uint2*)(g_Wlo + grow + k);
        }
    }
    __syncthreads();

    float creg[2] = {0.f, 0.f};

    const int hrow = tid >> 2, hvec = tid & 3;
    const uint32_t sH_base = (uint32_t)__cvta_generic_to_shared(sH);
    const uint32_t dst_lane = (uint32_t)(hrow * SA + hvec * 8) * 2;
    const size_t gsrc_lane = (size_t)hrow * K + hvec * 8;

    const int pb0 = tid >> 3, phc = tid & 7;
    const int colg = nblk * 8 + phc;

    for (int t = 0; t < T_DIM; ++t) {
        const int rbuf = t & 1;
        const __nv_bfloat16* __restrict__ Hh = g_hhi[rbuf];
        const __nv_bfloat16* __restrict__ Hl = g_hlo[rbuf];

        float px[2][4];
#pragma unroll
        for (int half = 0; half < 2; ++half) {
            const int b = pb0 + half * 32;
            const float* xp = g_xg + ((size_t)b * T_DIM + t) * G_DIM + colg;
            px[half][0] = xp[0];
            px[half][1] = xp[H_DIM];
            px[half][2] = xp[2 * H_DIM];
            px[half][3] = xp[3 * H_DIM];
        }

        // ---- prologue: 2 pairs (stages 0..3), one commit per pair ----
#pragma unroll
        for (int p = 0; p < 2; ++p) {
#pragma unroll
            for (int q = 0; q < 2; ++q) {
                const int s = p * 2 + q;
                const uint32_t d = sH_base + (uint32_t)(s * 2 * STG_E) * 2 + dst_lane;
                cpasync16(d, Hh + gsrc_lane + (size_t)s * BK);
                cpasync16(d + STG_E * 2, Hl + gsrc_lane + (size_t)s * BK);
            }
            cp_commit();
        }

        float ahh[2][4], ahl[2][4], alh[2][4];
#pragma unroll
        for (int j = 0; j < 2; j++)
#pragma unroll
            for (int q = 0; q < 4; q++) { ahh[j][q] = 0.f; ahl[j][q] = 0.f; alh[j][q] = 0.f; }

        // ---- 16 paired iterations (32 kb total), ring of 6 stages ----
#pragma unroll 2
        for (int kb = 0; kb < NKB; kb += 2) {
            if (kb == NKB - 2) cp_wait<0>(); else cp_wait<1>();
            __syncthreads();
            // refill the pair consumed in the previous iteration
            if (kb + 4 < NKB) {
#pragma unroll
                for (int q = 0; q < 2; ++q) {
                    const int s = kb + 4 + q;
                    const uint32_t d = sH_base
                        + (uint32_t)((s % NSTAGE) * 2 * STG_E) * 2 + dst_lane;
                    cpasync16(d, Hh + gsrc_lane + (size_t)s * BK);
                    cpasync16(d + STG_E * 2, Hl + gsrc_lane + (size_t)s * BK);
                }
                cp_commit();
            }
            // process stages kb, kb+1 (same order as R12)
#pragma unroll
            for (int kk = 0; kk < 2; ++kk) {
                const int kbb = kb + kk;
                const int slot = kbb % NSTAGE;
                const __nv_bfloat16* sHh_s = sH + slot * 2 * STG_E;
                const __nv_bfloat16* sHl_s = sHh_s + STG_E;
#pragma unroll
                for (int ks = 0; ks < 2; ++ks) {
                    const int k16 = ks * 16;
                    uint32_t ah[4], al[4], tWh[4], tWl[4];
                    ldsm4(ah, &sHh_s[(wr * 16) * SA + k16 + aofs]);
                    ldsm4(al, &sHl_s[(wr * 16) * SA + k16 + aofs]);
                    ldsm4(tWh, &sWh[wofs + kbb * 32 + k16]);
                    ldsm4(tWl, &sWl[wofs + kbb * 32 + k16]);
#pragma unroll
                    for (int j = 0; j < 2; ++j) {
                        mma_bf16(ahh[j], ah, tWh[j], tWh[j + 2]);
                        mma_bf16(ahl[j], ah, tWl[j], tWl[j + 2]);
                        mma_bf16(alh[j], al, tWh[j], tWh[j + 2]);
                    }
                }
            }
        }

        // gates -> shared
#pragma unroll
        for (int j = 0; j < 2; ++j) {
            const int m = wr * 16 + gid;
            const int c = wc * 16 + j * 8 + tg * 2;
            sG[m * 33 + c]     = ahh[j][0] + ahl[j][0] + alh[j][0];
            sG[m * 33 + c + 1] = ahh[j][1] + ahl[j][1] + alh[j][1];
            sG[(m + 8) * 33 + c]     = ahh[j][2] + ahl[j][2] + alh[j][2];
            sG[(m + 8) * 33 + c + 1] = ahh[j][3] + ahl[j][3] + alh[j][3];
        }
        __syncthreads();

        // pointwise LSTM update; c in registers (R12 verbatim)
        const int wb = rbuf ^ 1;
#pragma unroll
        for (int half = 0; half < 2; ++half) {
            const int b = pb0 + half * 32;
            const float vi = sG[b * 33 + phc]      + px[half][0];
            const float vf = sG[b * 33 + 8 + phc]  + px[half][1];
            const float vg = sG[b * 33 + 16 + phc] + px[half][2];
            const float vo = sG[b * 33 + 24 + phc] + px[half][3];
            const float ii = 1.f / (1.f + __expf(-vi));
            const float ff = 1.f / (1.f + __expf(-vf));
            const float gg = tanhf(vg);
            const float oo = 1.f / (1.f + __expf(-vo));
            const float cn = ff * creg[half] + ii * gg;
            creg[half] = cn;
            const float hn = oo * tanhf(cn);
            const __nv_bfloat16 hi = __float2bfloat16(hn);
            const __nv_bfloat16 lo = __float2bfloat16(hn - __bfloat162float(hi));
            const int cidx = b * H_DIM + colg;
            g_hhi[wb][cidx] = hi;
            g_hlo[wb][cidx] = lo;
            const size_t ooff = ((size_t)b * T_DIM + t) * H_DIM + colg;
            if (layer == 0) { g_Ahi[ooff] = hi; g_Alo[ooff] = lo; }
            else            { out[ooff] = hn; }
            if (t == T_DIM - 1) { g_h[cidx] = hn; g_c[cidx] = cn; }
        }

        // ---- grid-wide barrier (R12 verbatim) ----
        __threadfence();
        __syncthreads();
        if (tid == 0) {
            atomicAdd((unsigned*)&g_bar_count, 1u);
            const unsigned target = (unsigned)(t + 1) * (unsigned)gridDim.x;
            while (g_bar_count < target) { }
            __threadfence();
        }
        __syncthreads();
    }
}

// -------------------- host entry -------------------------------------------
extern "C" void kernel_launch(void* const* d_in, const int* in_sizes, int n_in,
                              void* d_out, int out_size) {
    if (n_in < 9) return;
    const float* X    = (const float*)d_in[0];
    const float* Wih0 = (const float*)d_in[1];
    const float* bih0 = (const float*)d_in[2];
    const float* Whh0 = (const float*)d_in[3];
    const float* bhh0 = (const float*)d_in[4];
    const float* Wih1 = (const float*)d_in[5];
    const float* bih1 = (const float*)d_in[6];
    const float* Whh1 = (const float*)d_in[7];
    const float* bhh1 = (const float*)d_in[8];
    float* out = (float*)d_out;

    cudaFuncSetAttribute(lstm_seq_kernel,
                         cudaFuncAttributeMaxDynamicSharedMemorySize, SMEM_SEQ);

    const size_t OUT1 = (size_t)M_TOT * H_DIM;
    const size_t BH   = (size_t)B_DIM * H_DIM;
    const bool write_states = (size_t)out_size >= OUT1 + 4 * BH;

    // slots: 0=Wih0, 1=Whh0, 2=Wih1, 3=Whh1
    split_all_kernel<<<3072, 256>>>(X, Wih0, Whh0, Wih1, Whh1);        // 0
    zero_state_kernel<<<256, 256>>>();                                 // 1
    gemm_xg_kernel<<<dim3(G_DIM / 64, M_TOT / 64), 256>>>(0, bih0, bhh0); // 2
    lstm_seq_kernel<<<NCTA, 256, SMEM_SEQ>>>(1, 0, out);               // 3 <- capture
    if (write_states)
        copy_state_kernel<<<256, 256>>>(out + OUT1, out + OUT1 + 2 * BH);

    gemm_xg_kernel<<<dim3(G_DIM / 64, M_TOT / 64), 256>>>(2, bih1, bhh1);
    zero_state_kernel<<<256, 256>>>();
    lstm_seq_kernel<<<NCTA, 256, SMEM_SEQ>>>(3, 1, out);
    if (write_states)
        copy_state_kernel<<<256, 256>>>(out + OUT1 + BH, out + OUT1 + 3 * BH);
}

// round 16
// speedup vs baseline: 1.2199x; 1.2199x over previous
#include <cuda_runtime.h>
#include <cuda_bf16.h>
#include <cstdint>

// ---------------------------------------------------------------------------
// 2-layer LSTM: B=64, T=512, D=H=1024.  HMMA (mma.sync) path.
// R16 = R12 trunk + ONE change: the recurrence H pipeline is split into 4
// independent PAIR pipelines (warps {w,w+4} share m-rows). Each pair owns a
// private 4-stage ring of its 16 H rows and syncs with bar.sync(1+wr, 64)
// instead of CTA-wide __syncthreads (32x/step skew coupling removed).
// Same bytes, same stage geometry, same accumulation order -> bit-identical.
// ---------------------------------------------------------------------------

#define B_DIM 64
#define T_DIM 512
#define H_DIM 1024
#define G_DIM 4096
#define M_TOT (B_DIM * T_DIM)   // 32768
#define NCTA 128

#define WS 1032          // padded W row stride (bf16 elems)
#define SA 40            // padded H stage row stride (elems)
#define PSTG (16 * SA)   // 640 elems per pair hi (or lo) stage
#define NSTAGE 4
// pair region: NSTAGE * 2 * PSTG elems; 4 pairs total = 40960 elems (same as R12)
#define SMEM_SEQ (32 * WS * 2 * 2 + 4 * NSTAGE * 2 * PSTG * 2 + 64 * 33 * 4)

// -------------------- device scratch (no allocs allowed) -------------------
__device__ __nv_bfloat16 g_Ahi[(size_t)M_TOT * H_DIM];   // X split, then out0 split
__device__ __nv_bfloat16 g_Alo[(size_t)M_TOT * H_DIM];
__device__ float         g_xg [(size_t)M_TOT * G_DIM];   // gate pre-activations
__device__ __nv_bfloat16 g_Whi[(size_t)4 * G_DIM * H_DIM];  // Wih0,Whh0,Wih1,Whh1
__device__ __nv_bfloat16 g_Wlo[(size_t)4 * G_DIM * H_DIM];
__device__ float         g_c[B_DIM * H_DIM];
__device__ float         g_h[B_DIM * H_DIM];
__device__ __nv_bfloat16 g_hhi[2][B_DIM * H_DIM];        // double-buffered h split
__device__ __nv_bfloat16 g_hlo[2][B_DIM * H_DIM];
__device__ volatile unsigned g_bar_count;

extern __shared__ char smem_raw[];

// -------------------- PTX helpers ------------------------------------------
__device__ __forceinline__ void mma_bf16(float (&d)[4], const uint32_t (&a)[4],
                                         uint32_t b0, uint32_t b1) {
    asm volatile(
        "mma.sync.aligned.m16n8k16.row.col.f32.bf16.bf16.f32 "
        "{%0,%1,%2,%3}, {%4,%5,%6,%7}, {%8,%9}, {%0,%1,%2,%3};\n"
        : "+f"(d[0]), "+f"(d[1]), "+f"(d[2]), "+f"(d[3])
        : "r"(a[0]), "r"(a[1]), "r"(a[2]), "r"(a[3]), "r"(b0), "r"(b1));
}
__device__ __forceinline__ void ldsm4(uint32_t (&r)[4], const __nv_bfloat16* p) {
    uint32_t a = (uint32_t)__cvta_generic_to_shared(p);
    asm volatile("ldmatrix.sync.aligned.m8n8.x4.shared.b16 {%0,%1,%2,%3}, [%4];"
                 : "=r"(r[0]), "=r"(r[1]), "=r"(r[2]), "=r"(r[3]) : "r"(a));
}
__device__ __forceinline__ void cpasync16(uint32_t dst, const void* src) {
    asm volatile("cp.async.cg.shared.global [%0], [%1], 16;" :: "r"(dst), "l"(src));
}
__device__ __forceinline__ void cp_commit() {
    asm volatile("cp.async.commit_group;");
}
template <int N>
__device__ __forceinline__ void cp_wait() {
    asm volatile("cp.async.wait_group %0;" :: "n"(N));
}
__device__ __forceinline__ void barn(int id, int cnt) {
    asm volatile("bar.sync %0, %1;" :: "r"(id), "r"(cnt) : "memory");
}

// -------------------- fused split: all 5 tensors in one launch --------------
__global__ void split_all_kernel(const float* __restrict__ X,
                                 const float* __restrict__ Wa,
                                 const float* __restrict__ Wb,
                                 const float* __restrict__ Wc,
                                 const float* __restrict__ Wd) {
    const size_t NQX = (size_t)M_TOT * H_DIM / 4;       // 8388608
    const size_t NQW = (size_t)G_DIM * H_DIM / 4;       // 1048576 = 1<<20
    const size_t TOT = NQX + 4 * NQW;
    for (size_t q = (size_t)blockIdx.x * blockDim.x + threadIdx.x; q < TOT;
         q += (size_t)gridDim.x * blockDim.x) {
        const float* src;
        __nv_bfloat16 *hi, *lo;
        size_t i;
        if (q < NQX) {
            src = X; i = q * 4; hi = g_Ahi; lo = g_Alo;
        } else {
            const size_t r = q - NQX;
            const int seg = (int)(r >> 20);
            i = (r - ((size_t)seg << 20)) * 4;
            src = (seg == 0) ? Wa : (seg == 1) ? Wb : (seg == 2) ? Wc : Wd;
            hi = g_Whi + (size_t)seg * G_DIM * H_DIM;
            lo = g_Wlo + (size_t)seg * G_DIM * H_DIM;
        }
        float4 v = *(const float4*)(src + i);
        __nv_bfloat16 h0 = __float2bfloat16(v.x);
        __nv_bfloat16 h1 = __float2bfloat16(v.y);
        __nv_bfloat16 h2 = __float2bfloat16(v.z);
        __nv_bfloat16 h3 = __float2bfloat16(v.w);
        __nv_bfloat16 l0 = __float2bfloat16(v.x - __bfloat162float(h0));
        __nv_bfloat16 l1 = __float2bfloat16(v.y - __bfloat162float(h1));
        __nv_bfloat16 l2 = __float2bfloat16(v.z - __bfloat162float(h2));
        __nv_bfloat16 l3 = __float2bfloat16(v.w - __bfloat162float(h3));
        __nv_bfloat162* ph = reinterpret_cast<__nv_bfloat162*>(hi + i);
        __nv_bfloat162* pl = reinterpret_cast<__nv_bfloat162*>(lo + i);
        ph[0] = __halves2bfloat162(h0, h1);
        ph[1] = __halves2bfloat162(h2, h3);
        pl[0] = __halves2bfloat162(l0, l1);
        pl[1] = __halves2bfloat162(l2, l3);
    }
}

__global__ void zero_state_kernel() {
    int i = blockIdx.x * blockDim.x + threadIdx.x;
    if (i == 0) g_bar_count = 0u;
    if (i < B_DIM * H_DIM) {
        g_h[i] = 0.f; g_c[i] = 0.f;
        __nv_bfloat16 z = __float2bfloat16(0.f);
        g_hhi[0][i] = z; g_hhi[1][i] = z;
        g_hlo[0][i] = z; g_hlo[1][i] = z;
    }
}

__global__ void copy_state_kernel(float* __restrict__ dh, float* __restrict__ dc) {
    int i = blockIdx.x * blockDim.x + threadIdx.x;
    if (i < B_DIM * H_DIM) { dh[i] = g_h[i]; dc[i] = g_c[i]; }
}

// -------------------- big GEMM: g_xg = A @ W^T + b1 + b2 (R7 verbatim) -----
__global__ __launch_bounds__(256) void gemm_xg_kernel(int wsel,
                                                      const float* __restrict__ b1,
                                                      const float* __restrict__ b2) {
    constexpr int BM = 64, BN = 64, BK = 32, GSA = 40, GSB = 40;
    constexpr int K = H_DIM, NKB = K / BK;
    __shared__ __nv_bfloat16 sAh[2][BM * GSA];
    __shared__ __nv_bfloat16 sAl[2][BM * GSA];
    __shared__ __nv_bfloat16 sBh[2][BN * GSB];
    __shared__ __nv_bfloat16 sBl[2][BN * GSB];

    const int m0 = blockIdx.y * BM;
    const int n0 = blockIdx.x * BN;
    const int tid = threadIdx.x;
    const int lane = tid & 31, wid = tid >> 5;
    const int wr = wid & 1;        // m strip (2 x 32)
    const int wc = wid >> 1;       // n strip (4 x 16)
    const int gid = lane >> 2, tg = lane & 3;

    const int aofs = (lane & 15) * GSA + (lane >> 4) * 8;
    const int bofs = (lane & 15) * GSB + (lane >> 4) * 8;

    const size_t woff = (size_t)wsel * G_DIM * H_DIM;
    const __nv_bfloat16* __restrict__ Wh = g_Whi + woff;
    const __nv_bfloat16* __restrict__ Wl = g_Wlo + woff;

    const int lrow = tid >> 2, lvec = tid & 3;            // 64 rows x 4 uint4
    const size_t aoff = (size_t)(m0 + lrow) * K + lvec * 8;
    const size_t boff = (size_t)(n0 + lrow) * K + lvec * 8;
    const int soff = lrow * GSA + lvec * 8;

    float acc[2][2][4];
#pragma unroll
    for (int i = 0; i < 2; i++)
#pragma unroll
        for (int j = 0; j < 2; j++)
#pragma unroll
            for (int q = 0; q < 4; q++) acc[i][j][q] = 0.f;

    uint4 rAh, rAl, rBh, rBl;
    rAh = *(const uint4*)(g_Ahi + aoff);
    rAl = *(const uint4*)(g_Alo + aoff);
    rBh = *(const uint4*)(Wh + boff);
    rBl = *(const uint4*)(Wl + boff);
    *(uint4*)&sAh[0][soff] = rAh;
    *(uint4*)&sAl[0][soff] = rAl;
    *(uint4*)&sBh[0][soff] = rBh;
    *(uint4*)&sBl[0][soff] = rBl;
    __syncthreads();

    for (int kb = 0; kb < NKB; ++kb) {
        const int buf = kb & 1;
        if (kb + 1 < NKB) {
            const size_t k2 = (size_t)(kb + 1) * BK;
            rAh = *(const uint4*)(g_Ahi + aoff + k2);
            rAl = *(const uint4*)(g_Alo + aoff + k2);
            rBh = *(const uint4*)(Wh + boff + k2);
            rBl = *(const uint4*)(Wl + boff + k2);
        }
#pragma unroll
        for (int ks = 0; ks < 2; ++ks) {
            const int k16 = ks * 16;
            uint32_t ah[2][4], al[2][4], tbh[4], tbl[4];
#pragma unroll
            for (int im = 0; im < 2; ++im) {
                const int mrow = wr * 32 + im * 16;
                ldsm4(ah[im], &sAh[buf][mrow * GSA + k16 + aofs]);
                ldsm4(al[im], &sAl[buf][mrow * GSA + k16 + aofs]);
            }
            ldsm4(tbh, &sBh[buf][(wc * 16) * GSB + k16 + bofs]);
            ldsm4(tbl, &sBl[buf][(wc * 16) * GSB + k16 + bofs]);
#pragma unroll
            for (int im = 0; im < 2; ++im) {
                mma_bf16(acc[im][0], ah[im], tbh[0], tbh[2]);
                mma_bf16(acc[im][0], ah[im], tbl[0], tbl[2]);
                mma_bf16(acc[im][0], al[im], tbh[0], tbh[2]);
                mma_bf16(acc[im][1], ah[im], tbh[1], tbh[3]);
                mma_bf16(acc[im][1], ah[im], tbl[1], tbl[3]);
                mma_bf16(acc[im][1], al[im], tbh[1], tbh[3]);
            }
        }
        if (kb + 1 < NKB) {
            const int nb = buf ^ 1;
            *(uint4*)&sAh[nb][soff] = rAh;
            *(uint4*)&sAl[nb][soff] = rAl;
            *(uint4*)&sBh[nb][soff] = rBh;
            *(uint4*)&sBl[nb][soff] = rBl;
        }
        __syncthreads();
    }

#pragma unroll
    for (int im = 0; im < 2; ++im)
#pragma unroll
        for (int in_ = 0; in_ < 2; ++in_) {
            const int row = m0 + wr * 32 + im * 16 + gid;
            const int col = n0 + wc * 16 + in_ * 8 + tg * 2;
            const float bb0 = b1[col] + b2[col];
            const float bb1 = b1[col + 1] + b2[col + 1];
            float2 v0 = make_float2(acc[im][in_][0] + bb0, acc[im][in_][1] + bb1);
            float2 v1 = make_float2(acc[im][in_][2] + bb0, acc[im][in_][3] + bb1);
            *(float2*)&g_xg[(size_t)row * G_DIM + col] = v0;
            *(float2*)&g_xg[(size_t)(row + 8) * G_DIM + col] = v1;
        }
}

// -------------------- persistent recurrence kernel (R12 + pair pipelines) ---
__global__ __launch_bounds__(256) void lstm_seq_kernel(int wsel, int layer,
                                                       float* __restrict__ out) {
    constexpr int BK = 32, K = H_DIM, NKB = K / BK;
    __nv_bfloat16* sWh = (__nv_bfloat16*)smem_raw;                    // 32*WS
    __nv_bfloat16* sWl = sWh + 32 * WS;                               // 32*WS
    __nv_bfloat16* sH  = sWl + 32 * WS;          // 4 pair regions
    float*         sG  = (float*)(sH + 4 * NSTAGE * 2 * PSTG);       // 64*33

    const int nblk = blockIdx.x;
    const int tid = threadIdx.x;
    const int lane = tid & 31, wid = tid >> 5;
    const int wr = wid & 3;          // 4 m-strips of 16 rows (pair id)
    const int wc = wid >> 2;         // 2 n-strips of 16 cols (pair member)
    const int gid = lane >> 2, tg = lane & 3;

    const int aofs = (lane & 15) * SA + (lane >> 4) * 8;      // H ldsm lane ofs
    const int wofs = (wc * 16 + (lane & 15)) * WS + (lane >> 4) * 8;  // W lane ofs

    const size_t woff = (size_t)wsel * G_DIM * H_DIM;

    // ---- load W_hh slice into smem (once) ----
    {
        const int wrow = tid >> 3, wvec = tid & 7;
        const int gsel = wrow >> 3, r8 = wrow & 7;
        const size_t grow = woff + (size_t)(gsel * H_DIM + nblk * 8 + r8) * K;
#pragma unroll 4
        for (int k = wvec * 4; k < K; k += 32) {
            *(uint2*)&sWh[wrow * WS + k] = *(const uint2*)(g_Whi + grow + k);
            *(uint2*)&sWl[wrow * WS + k] = *(const uint2*)(g_Wlo + grow + k);
        }
    }
    __syncthreads();

    float creg[2] = {0.f, 0.f};

    // pair-private pipeline: warps {wr, wr+4} share region wr.
    // 64 pair threads: ptid = wc*32 + lane; stage = 16 rows x 4 chunks (hi+lo).
    __nv_bfloat16* pairH = sH + wr * (NSTAGE * 2 * PSTG);
    const uint32_t pH_base = (uint32_t)__cvta_generic_to_shared(pairH);
    const int ptid = wc * 32 + lane;                 // 0..63
    const int prow = ptid >> 2;                      // 0..15
    const int pchk = ptid & 3;                       // 0..3 (16B chunks)
    const uint32_t pdst = (uint32_t)(prow * SA + pchk * 8) * 2;    // bytes
    const size_t pgsrc = (size_t)(wr * 16 + prow) * K + pchk * 8;
    const int barid = 1 + wr;                        // named barrier per pair

    const int pb0 = tid >> 3, phc = tid & 7;
    const int colg = nblk * 8 + phc;

    for (int t = 0; t < T_DIM; ++t) {
        const int rbuf = t & 1;
        const __nv_bfloat16* __restrict__ Hh = g_hhi[rbuf];
        const __nv_bfloat16* __restrict__ Hl = g_hlo[rbuf];

        float px[2][4];
#pragma unroll
        for (int half = 0; half < 2; ++half) {
            const int b = pb0 + half * 32;
            const float* xp = g_xg + ((size_t)b * T_DIM + t) * G_DIM + colg;
            px[half][0] = xp[0];
            px[half][1] = xp[H_DIM];
            px[half][2] = xp[2 * H_DIM];
            px[half][3] = xp[3 * H_DIM];
        }

        // ---- prologue: stages 0..2 (pair-private) ----
#pragma unroll
        for (int s = 0; s < NSTAGE - 1; ++s) {
            const uint32_t d = pH_base + (uint32_t)(s * 2 * PSTG) * 2 + pdst;
            cpasync16(d, Hh + pgsrc + (size_t)s * BK);
            cpasync16(d + PSTG * 2, Hl + pgsrc + (size_t)s * BK);
            cp_commit();
        }

        float ahh[2][4], ahl[2][4], alh[2][4];
#pragma unroll
        for (int j = 0; j < 2; j++)
#pragma unroll
            for (int q = 0; q < 4; q++) { ahh[j][q] = 0.f; ahl[j][q] = 0.f; alh[j][q] = 0.f; }

#pragma unroll 4
        for (int kb = 0; kb < NKB; ++kb) {
            cp_wait<2>();
            barn(barid, 64);
            if (kb + NSTAGE - 1 < NKB) {
                const int s = kb + NSTAGE - 1;
                const uint32_t d = pH_base + (uint32_t)((s & 3) * 2 * PSTG) * 2 + pdst;
                cpasync16(d, Hh + pgsrc + (size_t)s * BK);
                cpasync16(d + PSTG * 2, Hl + pgsrc + (size_t)s * BK);
            }
            cp_commit();

            const int slot = kb & 3;
            const __nv_bfloat16* sHh_s = pairH + slot * 2 * PSTG;
            const __nv_bfloat16* sHl_s = sHh_s + PSTG;

#pragma unroll
            for (int ks = 0; ks < 2; ++ks) {
                const int k16 = ks * 16;
                uint32_t ah[4], al[4], tWh[4], tWl[4];
                ldsm4(ah, &sHh_s[k16 + aofs]);
                ldsm4(al, &sHl_s[k16 + aofs]);
                ldsm4(tWh, &sWh[wofs + kb * BK + k16]);
                ldsm4(tWl, &sWl[wofs + kb * BK + k16]);
#pragma unroll
                for (int j = 0; j < 2; ++j) {
                    mma_bf16(ahh[j], ah, tWh[j], tWh[j + 2]);
                    mma_bf16(ahl[j], ah, tWl[j], tWl[j + 2]);
                    mma_bf16(alh[j], al, tWh[j], tWh[j + 2]);
                }
            }
        }

        // gates -> shared
#pragma unroll
        for (int j = 0; j < 2; ++j) {
            const int m = wr * 16 + gid;
            const int c = wc * 16 + j * 8 + tg * 2;
            sG[m * 33 + c]     = ahh[j][0] + ahl[j][0] + alh[j][0];
            sG[m * 33 + c + 1] = ahh[j][1] + ahl[j][1] + alh[j][1];
            sG[(m + 8) * 33 + c]     = ahh[j][2] + ahl[j][2] + alh[j][2];
            sG[(m + 8) * 33 + c + 1] = ahh[j][3] + ahl[j][3] + alh[j][3];
        }
        __syncthreads();

        // pointwise LSTM update; c in registers (R12 verbatim)
        const int wb = rbuf ^ 1;
#pragma unroll
        for (int half = 0; half < 2; ++half) {
            const int b = pb0 + half * 32;
            const float vi = sG[b * 33 + phc]      + px[half][0];
            const float vf = sG[b * 33 + 8 + phc]  + px[half][1];
            const float vg = sG[b * 33 + 16 + phc] + px[half][2];
            const float vo = sG[b * 33 + 24 + phc] + px[half][3];
            const float ii = 1.f / (1.f + __expf(-vi));
            const float ff = 1.f / (1.f + __expf(-vf));
            const float gg = tanhf(vg);
            const float oo = 1.f / (1.f + __expf(-vo));
            const float cn = ff * creg[half] + ii * gg;
            creg[half] = cn;
            const float hn = oo * tanhf(cn);
            const __nv_bfloat16 hi = __float2bfloat16(hn);
            const __nv_bfloat16 lo = __float2bfloat16(hn - __bfloat162float(hi));
            const int cidx = b * H_DIM + colg;
            g_hhi[wb][cidx] = hi;
            g_hlo[wb][cidx] = lo;
            const size_t ooff = ((size_t)b * T_DIM + t) * H_DIM + colg;
            if (layer == 0) { g_Ahi[ooff] = hi; g_Alo[ooff] = lo; }
            else            { out[ooff] = hn; }
            if (t == T_DIM - 1) { g_h[cidx] = hn; g_c[cidx] = cn; }
        }

        // ---- grid-wide barrier (R12 verbatim) ----
        __threadfence();
        __syncthreads();
        if (tid == 0) {
            atomicAdd((unsigned*)&g_bar_count, 1u);
            const unsigned target = (unsigned)(t + 1) * (unsigned)gridDim.x;
            while (g_bar_count < target) { }
            __threadfence();
        }
        __syncthreads();
    }
}

// -------------------- host entry -------------------------------------------
extern "C" void kernel_launch(void* const* d_in, const int* in_sizes, int n_in,
                              void* d_out, int out_size) {
    if (n_in < 9) return;
    const float* X    = (const float*)d_in[0];
    const float* Wih0 = (const float*)d_in[1];
    const float* bih0 = (const float*)d_in[2];
    const float* Whh0 = (const float*)d_in[3];
    const float* bhh0 = (const float*)d_in[4];
    const float* Wih1 = (const float*)d_in[5];
    const float* bih1 = (const float*)d_in[6];
    const float* Whh1 = (const float*)d_in[7];
    const float* bhh1 = (const float*)d_in[8];
    float* out = (float*)d_out;

    cudaFuncSetAttribute(lstm_seq_kernel,
                         cudaFuncAttributeMaxDynamicSharedMemorySize, SMEM_SEQ);

    const size_t OUT1 = (size_t)M_TOT * H_DIM;
    const size_t BH   = (size_t)B_DIM * H_DIM;
    const bool write_states = (size_t)out_size >= OUT1 + 4 * BH;

    // slots: 0=Wih0, 1=Whh0, 2=Wih1, 3=Whh1
    split_all_kernel<<<3072, 256>>>(X, Wih0, Whh0, Wih1, Whh1);        // 0
    zero_state_kernel<<<256, 256>>>();                                 // 1
    gemm_xg_kernel<<<dim3(G_DIM / 64, M_TOT / 64), 256>>>(0, bih0, bhh0); // 2
    lstm_seq_kernel<<<NCTA, 256, SMEM_SEQ>>>(1, 0, out);               // 3 <- capture
    if (write_states)
        copy_state_kernel<<<256, 256>>>(out + OUT1, out + OUT1 + 2 * BH);

    gemm_xg_kernel<<<dim3(G_DIM / 64, M_TOT / 64), 256>>>(2, bih1, bhh1);
    zero_state_kernel<<<256, 256>>>();
    lstm_seq_kernel<<<NCTA, 256, SMEM_SEQ>>>(3, 1, out);
    if (write_states)
        copy_state_kernel<<<256, 256>>>(out + OUT1 + BH, out + OUT1 + 3 * BH);
}